// round 4
// baseline (speedup 1.0000x reference)
#include <cuda_runtime.h>
#include <math.h>

#define D 128
#define MAXN 50048
#define MAXE 800000
#define MAXB 1024
#define BM 64

// ---------------- device scratch (static globals: allocation-free) -------------
__device__ int g_deg[MAXN];
__device__ int g_off[MAXN + 1];
__device__ int g_cur[MAXN];
__device__ int g_csr[MAXE];
__device__ float g_y[MAXN * D];   // x @ Wl  (pre-aggregation messages)
__device__ float g_r[MAXN * D];   // x @ Wr  (self term)
__device__ float g_hA[MAXN * D];
__device__ float g_hB[MAXN * D];
__device__ unsigned g_pool[MAXB * D];
__device__ int g_root[MAXB];

// ---------------- CSR build ---------------------------------------------------
__global__ void k_count(const int* __restrict__ dst, int E) {
    int e = blockIdx.x * blockDim.x + threadIdx.x;
    if (e < E) atomicAdd(&g_deg[dst[e]], 1);
}

// single-block inclusive scan over degrees -> exclusive offsets
__global__ void k_scan(int n) {
    __shared__ int s[1024];
    __shared__ int carry;
    int tid = threadIdx.x;
    if (tid == 0) { carry = 0; g_off[0] = 0; }
    __syncthreads();
    for (int base = 0; base < n; base += 1024) {
        int v = (base + tid < n) ? g_deg[base + tid] : 0;
        s[tid] = v;
        __syncthreads();
        for (int d2 = 1; d2 < 1024; d2 <<= 1) {
            int t = (tid >= d2) ? s[tid - d2] : 0;
            __syncthreads();
            s[tid] += t;
            __syncthreads();
        }
        int total = s[1023];
        if (base + tid < n) g_off[base + tid + 1] = carry + s[tid];
        __syncthreads();
        if (tid == 0) carry += total;
        __syncthreads();
    }
}

__global__ void k_fill(const int* __restrict__ src, const int* __restrict__ dst, int E) {
    int e = blockIdx.x * blockDim.x + threadIdx.x;
    if (e < E) {
        int d = dst[e];
        int p = atomicAdd(&g_cur[d], 1);
        g_csr[g_off[d] + p] = src[e];
    }
}

// ---------------- fused dual GEMM: y = feat@Wl, r = feat@Wr -------------------
// BM=64 rows/block, 256 output cols (128 for Wl, 128 for Wr), K=128 in one shot.
// 256 threads, thread tile 4 rows x 16 cols. Weights + feat tile in dyn smem.
__global__ void __launch_bounds__(256)
k_gemm(const float* __restrict__ feat, const float* __restrict__ Wl,
       const float* __restrict__ Wr, float* __restrict__ y,
       float* __restrict__ r, int n) {
    extern __shared__ float smem[];
    float* Ws = smem;              // [128][256] = 128 KB
    float* As = smem + D * 256;    // [64][128]  =  32 KB
    int tid = threadIdx.x;

    // load weights into smem, Ws[k][c]: c<128 -> Wl, c>=128 -> Wr
    const float4* wl4 = (const float4*)Wl;
    const float4* wr4 = (const float4*)Wr;
    for (int i = tid; i < D * D / 4; i += 256) {
        int k = (i * 4) / D, c = (i * 4) % D;
        *(float4*)&Ws[k * 256 + c]       = wl4[i];
        *(float4*)&Ws[k * 256 + c + 128] = wr4[i];
    }
    // load 64-row feature tile
    int rb = blockIdx.x * BM;
    const float4* f4 = (const float4*)feat;
    for (int i = tid; i < BM * D / 4; i += 256) {
        int rr = (i * 4) / D, cc = (i * 4) % D;
        int row = rb + rr;
        float4 v = make_float4(0.f, 0.f, 0.f, 0.f);
        if (row < n) v = f4[row * (D / 4) + cc / 4];
        *(float4*)&As[rr * D + cc] = v;
    }
    __syncthreads();

    int ty = tid >> 4, tx = tid & 15;
    float acc[4][16];
#pragma unroll
    for (int i = 0; i < 4; i++)
#pragma unroll
        for (int j = 0; j < 16; j++) acc[i][j] = 0.f;

#pragma unroll 4
    for (int k = 0; k < D; k++) {
        float a[4];
#pragma unroll
        for (int i = 0; i < 4; i++) a[i] = As[(ty * 4 + i) * D + k];
        float bb[16];
#pragma unroll
        for (int j = 0; j < 16; j += 4)
            *(float4*)&bb[j] = *(const float4*)&Ws[k * 256 + tx * 16 + j];
#pragma unroll
        for (int i = 0; i < 4; i++)
#pragma unroll
            for (int j = 0; j < 16; j++) acc[i][j] += a[i] * bb[j];
    }

#pragma unroll
    for (int i = 0; i < 4; i++) {
        int row = rb + ty * 4 + i;
        if (row >= n) continue;
#pragma unroll
        for (int j = 0; j < 16; j += 4) {
            int c = tx * 16 + j;
            float4 v = make_float4(acc[i][j], acc[i][j + 1], acc[i][j + 2], acc[i][j + 3]);
            if (c < 128) *(float4*)&y[row * D + c] = v;
            else         *(float4*)&r[row * D + (c - 128)] = v;
        }
    }
}

// ---------------- per-node mean aggregation + bias + self + relu --------------
// one warp per node; lane l owns 4 contiguous floats of the 128-dim row
__global__ void k_agg(const float* __restrict__ yl, const float* __restrict__ hr,
                      const float* __restrict__ bl, float* __restrict__ out, int n) {
    int warp = (blockIdx.x * blockDim.x + threadIdx.x) >> 5;
    int lane = threadIdx.x & 31;
    if (warp >= n) return;
    int beg = g_off[warp], end = g_off[warp + 1];
    float4 acc = make_float4(0.f, 0.f, 0.f, 0.f);
    for (int e = beg; e < end; e++) {
        int j = __ldg(&g_csr[e]);
        float4 v = *(const float4*)&yl[j * D + lane * 4];
        acc.x += v.x; acc.y += v.y; acc.z += v.z; acc.w += v.w;
    }
    float inv = 1.0f / fmaxf((float)(end - beg), 1.0f);
    float4 b = *(const float4*)&bl[lane * 4];
    float4 rr = *(const float4*)&hr[warp * D + lane * 4];
    float4 o;
    o.x = fmaxf(acc.x * inv + b.x + rr.x, 0.f);
    o.y = fmaxf(acc.y * inv + b.y + rr.y, 0.f);
    o.z = fmaxf(acc.z * inv + b.z + rr.z, 0.f);
    o.w = fmaxf(acc.w * inv + b.w + rr.w, 0.f);
    *(float4*)&out[warp * D + lane * 4] = o;
}

// ---------------- global max pool (uint-bit atomicMax, values >= 0) -----------
__global__ void k_pool(const float* __restrict__ h, const int* __restrict__ batch, int n) {
    int idx = blockIdx.x * blockDim.x + threadIdx.x;
    int node = idx >> 5, lane = idx & 31;
    if (node >= n) return;
    int b = batch[node];
    float4 v = *(const float4*)&h[node * D + lane * 4];
    atomicMax(&g_pool[b * D + lane * 4 + 0], __float_as_uint(v.x));
    atomicMax(&g_pool[b * D + lane * 4 + 1], __float_as_uint(v.y));
    atomicMax(&g_pool[b * D + lane * 4 + 2], __float_as_uint(v.z));
    atomicMax(&g_pool[b * D + lane * 4 + 3], __float_as_uint(v.w));
}

__global__ void k_root(const int* __restrict__ batch, int n) {
    int i = blockIdx.x * blockDim.x + threadIdx.x;
    if (i < n && (i == 0 || batch[i] != batch[i - 1])) g_root[batch[i]] = i;
}

// ---------------- fused MLP head, one block per graph --------------------------
__global__ void __launch_bounds__(128)
k_head(const float* __restrict__ x,
       const float* __restrict__ Wf1, const float* __restrict__ bf1,
       const float* __restrict__ Wf2, const float* __restrict__ bf2,
       const float* __restrict__ Wsm, const float* __restrict__ bsm,
       const float* __restrict__ Wnews, const float* __restrict__ bnews,
       const float* __restrict__ Wcat, const float* __restrict__ bcat,
       float* __restrict__ out) {
    int b = blockIdx.x, t = threadIdx.x;
    __shared__ float p[D], f1[256], f2[D], xr[D], tmp[4];
    p[t] = __uint_as_float(g_pool[b * D + t]);
    int r = g_root[b];
    xr[t] = x[r * D + t];
    __syncthreads();
    for (int o = t; o < 256; o += 128) {
        float a = bf1[o];
        for (int k = 0; k < D; k++) a += p[k] * Wf1[k * 256 + o];
        f1[o] = fmaxf(a, 0.f);
    }
    __syncthreads();
    {
        float a = bf2[t];
        for (int k = 0; k < 256; k++) a += f1[k] * Wf2[k * 128 + t];
        f2[t] = fmaxf(a, 0.f);
    }
    __syncthreads();
    if (t < 2) {
        float a = bsm[t];
        for (int k = 0; k < D; k++) a += f2[k] * Wsm[k * 2 + t];
        tmp[t] = fmaxf(a, 0.f);
    } else if (t < 4) {
        int o = t - 2;
        float a = bnews[o];
        for (int k = 0; k < D; k++) a += xr[k] * Wnews[k * 2 + o];
        tmp[t] = fmaxf(a, 0.f);
    }
    __syncthreads();
    if (t == 0) {
        float z = bcat[0];
        for (int j = 0; j < 4; j++) z += tmp[j] * Wcat[j];
        out[b] = 1.0f / (1.0f + expf(-z));
    }
}

// ---------------- launch -------------------------------------------------------
extern "C" void kernel_launch(void* const* d_in, const int* in_sizes, int n_in,
                              void* d_out, int out_size) {
    const float* x     = (const float*)d_in[0];
    const int*   edge  = (const int*)d_in[1];
    const int*   batch = (const int*)d_in[2];
    const float* Wl1 = (const float*)d_in[3];
    const float* Wr1 = (const float*)d_in[4];
    const float* bl1 = (const float*)d_in[5];
    const float* Wl2 = (const float*)d_in[6];
    const float* Wr2 = (const float*)d_in[7];
    const float* bl2 = (const float*)d_in[8];
    const float* Wl3 = (const float*)d_in[9];
    const float* Wr3 = (const float*)d_in[10];
    const float* bl3 = (const float*)d_in[11];
    const float* Wf1 = (const float*)d_in[12];
    const float* bf1 = (const float*)d_in[13];
    const float* Wf2 = (const float*)d_in[14];
    const float* bf2 = (const float*)d_in[15];
    const float* Wsm = (const float*)d_in[16];
    const float* bsm = (const float*)d_in[17];
    const float* Wnw = (const float*)d_in[18];
    const float* bnw = (const float*)d_in[19];
    const float* Wct = (const float*)d_in[20];
    const float* bct = (const float*)d_in[21];

    int N = in_sizes[0] / D;
    int E = in_sizes[1] / 2;
    int B = out_size;
    const int* src = edge;
    const int* dst = edge + E;

    void* p;
    cudaGetSymbolAddress(&p, g_deg);  cudaMemsetAsync(p, 0, (size_t)N * sizeof(int));
    cudaGetSymbolAddress(&p, g_cur);  cudaMemsetAsync(p, 0, (size_t)N * sizeof(int));
    cudaGetSymbolAddress(&p, g_pool); cudaMemsetAsync(p, 0, (size_t)B * D * sizeof(unsigned));

    float *yp, *rp, *hA, *hB;
    cudaGetSymbolAddress((void**)&yp, g_y);
    cudaGetSymbolAddress((void**)&rp, g_r);
    cudaGetSymbolAddress((void**)&hA, g_hA);
    cudaGetSymbolAddress((void**)&hB, g_hB);

    k_count<<<(E + 255) / 256, 256>>>(dst, E);
    k_scan<<<1, 1024>>>(N);
    k_fill<<<(E + 255) / 256, 256>>>(src, dst, E);

    size_t smem = (size_t)(D * 256 + BM * D) * sizeof(float);  // 160 KB
    cudaFuncSetAttribute(k_gemm, cudaFuncAttributeMaxDynamicSharedMemorySize, (int)smem);
    int gb = (N + BM - 1) / BM;
    int ga = ((N * 32) + 255) / 256;

    // layer 1: x -> hA
    k_gemm<<<gb, 256, smem>>>(x, Wl1, Wr1, yp, rp, N);
    k_agg<<<ga, 256>>>(yp, rp, bl1, hA, N);
    // layer 2: hA -> hB
    k_gemm<<<gb, 256, smem>>>(hA, Wl2, Wr2, yp, rp, N);
    k_agg<<<ga, 256>>>(yp, rp, bl2, hB, N);
    // layer 3: hB -> hA
    k_gemm<<<gb, 256, smem>>>(hB, Wl3, Wr3, yp, rp, N);
    k_agg<<<ga, 256>>>(yp, rp, bl3, hA, N);

    k_pool<<<ga, 256>>>(hA, batch, N);
    k_root<<<(N + 255) / 256, 256>>>(batch, N);
    k_head<<<B, 128>>>(x, Wf1, bf1, Wf2, bf2, Wsm, bsm, Wnw, bnw, Wct, bct, (float*)d_out);
}

// round 6
// speedup vs baseline: 1.0006x; 1.0006x over previous
#include <cuda_runtime.h>
#include <math.h>

#define D 128
#define MAXN 50048
#define MAXE 800000
#define MAXB 1024
#define BM 64

// ---------------- device scratch (static globals: allocation-free) -------------
__device__ int g_deg[MAXN];
__device__ int g_off[MAXN + 1];
__device__ int g_cur[MAXN];
__device__ int g_csr[MAXE];
__device__ float g_y[MAXN * D];   // x @ Wl  (pre-aggregation messages)
__device__ float g_r[MAXN * D];   // x @ Wr  (self term)
__device__ float g_hA[MAXN * D];
__device__ float g_hB[MAXN * D];
__device__ unsigned g_pool[MAXB * D];
__device__ int g_root[MAXB];

// ---------------- CSR build ---------------------------------------------------
__global__ void k_count(const int* __restrict__ dst, int E) {
    int e = blockIdx.x * blockDim.x + threadIdx.x;
    if (e < E) atomicAdd(&g_deg[dst[e]], 1);
}

// single-block inclusive scan over degrees -> exclusive offsets
__global__ void k_scan(int n) {
    __shared__ int s[1024];
    __shared__ int carry;
    int tid = threadIdx.x;
    if (tid == 0) { carry = 0; g_off[0] = 0; }
    __syncthreads();
    for (int base = 0; base < n; base += 1024) {
        int v = (base + tid < n) ? g_deg[base + tid] : 0;
        s[tid] = v;
        __syncthreads();
        for (int d2 = 1; d2 < 1024; d2 <<= 1) {
            int t = (tid >= d2) ? s[tid - d2] : 0;
            __syncthreads();
            s[tid] += t;
            __syncthreads();
        }
        int total = s[1023];
        if (base + tid < n) g_off[base + tid + 1] = carry + s[tid];
        __syncthreads();
        if (tid == 0) carry += total;
        __syncthreads();
    }
}

__global__ void k_fill(const int* __restrict__ src, const int* __restrict__ dst, int E) {
    int e = blockIdx.x * blockDim.x + threadIdx.x;
    if (e < E) {
        int d = dst[e];
        int p = atomicAdd(&g_cur[d], 1);
        g_csr[g_off[d] + p] = src[e];
    }
}

// ---------------- fused dual GEMM: y = feat@Wl, r = feat@Wr -------------------
// BM=64 rows/block, 256 output cols (128 for Wl, 128 for Wr), K=128 in one shot.
// 256 threads, thread tile 4 rows x 16 cols. Weights + feat tile in dyn smem.
__global__ void __launch_bounds__(256)
k_gemm(const float* __restrict__ feat, const float* __restrict__ Wl,
       const float* __restrict__ Wr, float* __restrict__ y,
       float* __restrict__ r, int n) {
    extern __shared__ float smem[];
    float* Ws = smem;              // [128][256] = 128 KB
    float* As = smem + D * 256;    // [64][128]  =  32 KB
    int tid = threadIdx.x;

    // load weights into smem, Ws[k][c]: c<128 -> Wl, c>=128 -> Wr
    const float4* wl4 = (const float4*)Wl;
    const float4* wr4 = (const float4*)Wr;
    for (int i = tid; i < D * D / 4; i += 256) {
        int k = (i * 4) / D, c = (i * 4) % D;
        *(float4*)&Ws[k * 256 + c]       = wl4[i];
        *(float4*)&Ws[k * 256 + c + 128] = wr4[i];
    }
    // load 64-row feature tile
    int rb = blockIdx.x * BM;
    const float4* f4 = (const float4*)feat;
    for (int i = tid; i < BM * D / 4; i += 256) {
        int rr = (i * 4) / D, cc = (i * 4) % D;
        int row = rb + rr;
        float4 v = make_float4(0.f, 0.f, 0.f, 0.f);
        if (row < n) v = f4[row * (D / 4) + cc / 4];
        *(float4*)&As[rr * D + cc] = v;
    }
    __syncthreads();

    int ty = tid >> 4, tx = tid & 15;
    float acc[4][16];
#pragma unroll
    for (int i = 0; i < 4; i++)
#pragma unroll
        for (int j = 0; j < 16; j++) acc[i][j] = 0.f;

#pragma unroll 4
    for (int k = 0; k < D; k++) {
        float a[4];
#pragma unroll
        for (int i = 0; i < 4; i++) a[i] = As[(ty * 4 + i) * D + k];
        float bb[16];
#pragma unroll
        for (int j = 0; j < 16; j += 4)
            *(float4*)&bb[j] = *(const float4*)&Ws[k * 256 + tx * 16 + j];
#pragma unroll
        for (int i = 0; i < 4; i++)
#pragma unroll
            for (int j = 0; j < 16; j++) acc[i][j] += a[i] * bb[j];
    }

#pragma unroll
    for (int i = 0; i < 4; i++) {
        int row = rb + ty * 4 + i;
        if (row >= n) continue;
#pragma unroll
        for (int j = 0; j < 16; j += 4) {
            int c = tx * 16 + j;
            float4 v = make_float4(acc[i][j], acc[i][j + 1], acc[i][j + 2], acc[i][j + 3]);
            if (c < 128) *(float4*)&y[row * D + c] = v;
            else         *(float4*)&r[row * D + (c - 128)] = v;
        }
    }
}

// ---------------- per-node mean aggregation + bias + self + relu --------------
// one warp per node; lane l owns 4 contiguous floats of the 128-dim row
__global__ void k_agg(const float* __restrict__ yl, const float* __restrict__ hr,
                      const float* __restrict__ bl, float* __restrict__ out, int n) {
    int warp = (blockIdx.x * blockDim.x + threadIdx.x) >> 5;
    int lane = threadIdx.x & 31;
    if (warp >= n) return;
    int beg = g_off[warp], end = g_off[warp + 1];
    float4 acc = make_float4(0.f, 0.f, 0.f, 0.f);
    for (int e = beg; e < end; e++) {
        int j = __ldg(&g_csr[e]);
        float4 v = *(const float4*)&yl[j * D + lane * 4];
        acc.x += v.x; acc.y += v.y; acc.z += v.z; acc.w += v.w;
    }
    float inv = 1.0f / fmaxf((float)(end - beg), 1.0f);
    float4 b = *(const float4*)&bl[lane * 4];
    float4 rr = *(const float4*)&hr[warp * D + lane * 4];
    float4 o;
    o.x = fmaxf(acc.x * inv + b.x + rr.x, 0.f);
    o.y = fmaxf(acc.y * inv + b.y + rr.y, 0.f);
    o.z = fmaxf(acc.z * inv + b.z + rr.z, 0.f);
    o.w = fmaxf(acc.w * inv + b.w + rr.w, 0.f);
    *(float4*)&out[warp * D + lane * 4] = o;
}

// ---------------- global max pool (uint-bit atomicMax, values >= 0) -----------
__global__ void k_pool(const float* __restrict__ h, const int* __restrict__ batch, int n) {
    int idx = blockIdx.x * blockDim.x + threadIdx.x;
    int node = idx >> 5, lane = idx & 31;
    if (node >= n) return;
    int b = batch[node];
    float4 v = *(const float4*)&h[node * D + lane * 4];
    atomicMax(&g_pool[b * D + lane * 4 + 0], __float_as_uint(v.x));
    atomicMax(&g_pool[b * D + lane * 4 + 1], __float_as_uint(v.y));
    atomicMax(&g_pool[b * D + lane * 4 + 2], __float_as_uint(v.z));
    atomicMax(&g_pool[b * D + lane * 4 + 3], __float_as_uint(v.w));
}

__global__ void k_root(const int* __restrict__ batch, int n) {
    int i = blockIdx.x * blockDim.x + threadIdx.x;
    if (i < n && (i == 0 || batch[i] != batch[i - 1])) g_root[batch[i]] = i;
}

// ---------------- fused MLP head, one block per graph --------------------------
__global__ void __launch_bounds__(128)
k_head(const float* __restrict__ x,
       const float* __restrict__ Wf1, const float* __restrict__ bf1,
       const float* __restrict__ Wf2, const float* __restrict__ bf2,
       const float* __restrict__ Wsm, const float* __restrict__ bsm,
       const float* __restrict__ Wnews, const float* __restrict__ bnews,
       const float* __restrict__ Wcat, const float* __restrict__ bcat,
       float* __restrict__ out) {
    int b = blockIdx.x, t = threadIdx.x;
    __shared__ float p[D], f1[256], f2[D], xr[D], tmp[4];
    p[t] = __uint_as_float(g_pool[b * D + t]);
    int r = g_root[b];
    xr[t] = x[r * D + t];
    __syncthreads();
    for (int o = t; o < 256; o += 128) {
        float a = bf1[o];
        for (int k = 0; k < D; k++) a += p[k] * Wf1[k * 256 + o];
        f1[o] = fmaxf(a, 0.f);
    }
    __syncthreads();
    {
        float a = bf2[t];
        for (int k = 0; k < 256; k++) a += f1[k] * Wf2[k * 128 + t];
        f2[t] = fmaxf(a, 0.f);
    }
    __syncthreads();
    if (t < 2) {
        float a = bsm[t];
        for (int k = 0; k < D; k++) a += f2[k] * Wsm[k * 2 + t];
        tmp[t] = fmaxf(a, 0.f);
    } else if (t < 4) {
        int o = t - 2;
        float a = bnews[o];
        for (int k = 0; k < D; k++) a += xr[k] * Wnews[k * 2 + o];
        tmp[t] = fmaxf(a, 0.f);
    }
    __syncthreads();
    if (t == 0) {
        float z = bcat[0];
        for (int j = 0; j < 4; j++) z += tmp[j] * Wcat[j];
        out[b] = 1.0f / (1.0f + expf(-z));
    }
}

// ---------------- launch -------------------------------------------------------
extern "C" void kernel_launch(void* const* d_in, const int* in_sizes, int n_in,
                              void* d_out, int out_size) {
    const float* x     = (const float*)d_in[0];
    const int*   edge  = (const int*)d_in[1];
    const int*   batch = (const int*)d_in[2];
    const float* Wl1 = (const float*)d_in[3];
    const float* Wr1 = (const float*)d_in[4];
    const float* bl1 = (const float*)d_in[5];
    const float* Wl2 = (const float*)d_in[6];
    const float* Wr2 = (const float*)d_in[7];
    const float* bl2 = (const float*)d_in[8];
    const float* Wl3 = (const float*)d_in[9];
    const float* Wr3 = (const float*)d_in[10];
    const float* bl3 = (const float*)d_in[11];
    const float* Wf1 = (const float*)d_in[12];
    const float* bf1 = (const float*)d_in[13];
    const float* Wf2 = (const float*)d_in[14];
    const float* bf2 = (const float*)d_in[15];
    const float* Wsm = (const float*)d_in[16];
    const float* bsm = (const float*)d_in[17];
    const float* Wnw = (const float*)d_in[18];
    const float* bnw = (const float*)d_in[19];
    const float* Wct = (const float*)d_in[20];
    const float* bct = (const float*)d_in[21];

    int N = in_sizes[0] / D;
    int E = in_sizes[1] / 2;
    int B = out_size;
    const int* src = edge;
    const int* dst = edge + E;

    void* p;
    cudaGetSymbolAddress(&p, g_deg);  cudaMemsetAsync(p, 0, (size_t)N * sizeof(int));
    cudaGetSymbolAddress(&p, g_cur);  cudaMemsetAsync(p, 0, (size_t)N * sizeof(int));
    cudaGetSymbolAddress(&p, g_pool); cudaMemsetAsync(p, 0, (size_t)B * D * sizeof(unsigned));

    float *yp, *rp, *hA, *hB;
    cudaGetSymbolAddress((void**)&yp, g_y);
    cudaGetSymbolAddress((void**)&rp, g_r);
    cudaGetSymbolAddress((void**)&hA, g_hA);
    cudaGetSymbolAddress((void**)&hB, g_hB);

    k_count<<<(E + 255) / 256, 256>>>(dst, E);
    k_scan<<<1, 1024>>>(N);
    k_fill<<<(E + 255) / 256, 256>>>(src, dst, E);

    size_t smem = (size_t)(D * 256 + BM * D) * sizeof(float);  // 160 KB
    cudaFuncSetAttribute(k_gemm, cudaFuncAttributeMaxDynamicSharedMemorySize, (int)smem);
    int gb = (N + BM - 1) / BM;
    int ga = ((N * 32) + 255) / 256;

    // layer 1: x -> hA
    k_gemm<<<gb, 256, smem>>>(x, Wl1, Wr1, yp, rp, N);
    k_agg<<<ga, 256>>>(yp, rp, bl1, hA, N);
    // layer 2: hA -> hB
    k_gemm<<<gb, 256, smem>>>(hA, Wl2, Wr2, yp, rp, N);
    k_agg<<<ga, 256>>>(yp, rp, bl2, hB, N);
    // layer 3: hB -> hA
    k_gemm<<<gb, 256, smem>>>(hB, Wl3, Wr3, yp, rp, N);
    k_agg<<<ga, 256>>>(yp, rp, bl3, hA, N);

    k_pool<<<ga, 256>>>(hA, batch, N);
    k_root<<<(N + 255) / 256, 256>>>(batch, N);
    k_head<<<B, 128>>>(x, Wf1, bf1, Wf2, bf2, Wsm, bsm, Wnw, bnw, Wct, bct, (float*)d_out);
}

// round 8
// speedup vs baseline: 1.0012x; 1.0006x over previous
#include <cuda_runtime.h>
#include <math.h>

#define D 128
#define MAXN 50048
#define MAXE 800000
#define MAXB 1024
#define BM 64

// ---------------- device scratch (static globals: allocation-free) -------------
__device__ int g_deg[MAXN];
__device__ int g_off[MAXN + 1];
__device__ int g_cur[MAXN];
__device__ int g_csr[MAXE];
__device__ float g_y[MAXN * D];   // x @ Wl  (pre-aggregation messages)
__device__ float g_r[MAXN * D];   // x @ Wr  (self term)
__device__ float g_hA[MAXN * D];
__device__ float g_hB[MAXN * D];
__device__ unsigned g_pool[MAXB * D];
__device__ int g_root[MAXB];

// ---------------- CSR build ---------------------------------------------------
__global__ void k_count(const int* __restrict__ dst, int E) {
    int e = blockIdx.x * blockDim.x + threadIdx.x;
    if (e < E) atomicAdd(&g_deg[dst[e]], 1);
}

// single-block inclusive scan over degrees -> exclusive offsets
__global__ void k_scan(int n) {
    __shared__ int s[1024];
    __shared__ int carry;
    int tid = threadIdx.x;
    if (tid == 0) { carry = 0; g_off[0] = 0; }
    __syncthreads();
    for (int base = 0; base < n; base += 1024) {
        int v = (base + tid < n) ? g_deg[base + tid] : 0;
        s[tid] = v;
        __syncthreads();
        for (int d2 = 1; d2 < 1024; d2 <<= 1) {
            int t = (tid >= d2) ? s[tid - d2] : 0;
            __syncthreads();
            s[tid] += t;
            __syncthreads();
        }
        int total = s[1023];
        if (base + tid < n) g_off[base + tid + 1] = carry + s[tid];
        __syncthreads();
        if (tid == 0) carry += total;
        __syncthreads();
    }
}

__global__ void k_fill(const int* __restrict__ src, const int* __restrict__ dst, int E) {
    int e = blockIdx.x * blockDim.x + threadIdx.x;
    if (e < E) {
        int d = dst[e];
        int p = atomicAdd(&g_cur[d], 1);
        g_csr[g_off[d] + p] = src[e];
    }
}

// ---------------- fused dual GEMM: y = feat@Wl, r = feat@Wr -------------------
// BM=64 rows/block, 256 output cols (128 for Wl, 128 for Wr), K=128 in one shot.
// 256 threads, thread tile 4 rows x 16 cols. Weights + feat tile in dyn smem.
__global__ void __launch_bounds__(256)
k_gemm(const float* __restrict__ feat, const float* __restrict__ Wl,
       const float* __restrict__ Wr, float* __restrict__ y,
       float* __restrict__ r, int n) {
    extern __shared__ float smem[];
    float* Ws = smem;              // [128][256] = 128 KB
    float* As = smem + D * 256;    // [64][128]  =  32 KB
    int tid = threadIdx.x;

    // load weights into smem, Ws[k][c]: c<128 -> Wl, c>=128 -> Wr
    const float4* wl4 = (const float4*)Wl;
    const float4* wr4 = (const float4*)Wr;
    for (int i = tid; i < D * D / 4; i += 256) {
        int k = (i * 4) / D, c = (i * 4) % D;
        *(float4*)&Ws[k * 256 + c]       = wl4[i];
        *(float4*)&Ws[k * 256 + c + 128] = wr4[i];
    }
    // load 64-row feature tile
    int rb = blockIdx.x * BM;
    const float4* f4 = (const float4*)feat;
    for (int i = tid; i < BM * D / 4; i += 256) {
        int rr = (i * 4) / D, cc = (i * 4) % D;
        int row = rb + rr;
        float4 v = make_float4(0.f, 0.f, 0.f, 0.f);
        if (row < n) v = f4[row * (D / 4) + cc / 4];
        *(float4*)&As[rr * D + cc] = v;
    }
    __syncthreads();

    int ty = tid >> 4, tx = tid & 15;
    float acc[4][16];
#pragma unroll
    for (int i = 0; i < 4; i++)
#pragma unroll
        for (int j = 0; j < 16; j++) acc[i][j] = 0.f;

#pragma unroll 4
    for (int k = 0; k < D; k++) {
        float a[4];
#pragma unroll
        for (int i = 0; i < 4; i++) a[i] = As[(ty * 4 + i) * D + k];
        float bb[16];
#pragma unroll
        for (int j = 0; j < 16; j += 4)
            *(float4*)&bb[j] = *(const float4*)&Ws[k * 256 + tx * 16 + j];
#pragma unroll
        for (int i = 0; i < 4; i++)
#pragma unroll
            for (int j = 0; j < 16; j++) acc[i][j] += a[i] * bb[j];
    }

#pragma unroll
    for (int i = 0; i < 4; i++) {
        int row = rb + ty * 4 + i;
        if (row >= n) continue;
#pragma unroll
        for (int j = 0; j < 16; j += 4) {
            int c = tx * 16 + j;
            float4 v = make_float4(acc[i][j], acc[i][j + 1], acc[i][j + 2], acc[i][j + 3]);
            if (c < 128) *(float4*)&y[row * D + c] = v;
            else         *(float4*)&r[row * D + (c - 128)] = v;
        }
    }
}

// ---------------- per-node mean aggregation + bias + self + relu --------------
// one warp per node; lane l owns 4 contiguous floats of the 128-dim row
__global__ void k_agg(const float* __restrict__ yl, const float* __restrict__ hr,
                      const float* __restrict__ bl, float* __restrict__ out, int n) {
    int warp = (blockIdx.x * blockDim.x + threadIdx.x) >> 5;
    int lane = threadIdx.x & 31;
    if (warp >= n) return;
    int beg = g_off[warp], end = g_off[warp + 1];
    float4 acc = make_float4(0.f, 0.f, 0.f, 0.f);
    for (int e = beg; e < end; e++) {
        int j = __ldg(&g_csr[e]);
        float4 v = *(const float4*)&yl[j * D + lane * 4];
        acc.x += v.x; acc.y += v.y; acc.z += v.z; acc.w += v.w;
    }
    float inv = 1.0f / fmaxf((float)(end - beg), 1.0f);
    float4 b = *(const float4*)&bl[lane * 4];
    float4 rr = *(const float4*)&hr[warp * D + lane * 4];
    float4 o;
    o.x = fmaxf(acc.x * inv + b.x + rr.x, 0.f);
    o.y = fmaxf(acc.y * inv + b.y + rr.y, 0.f);
    o.z = fmaxf(acc.z * inv + b.z + rr.z, 0.f);
    o.w = fmaxf(acc.w * inv + b.w + rr.w, 0.f);
    *(float4*)&out[warp * D + lane * 4] = o;
}

// ---------------- global max pool (uint-bit atomicMax, values >= 0) -----------
__global__ void k_pool(const float* __restrict__ h, const int* __restrict__ batch, int n) {
    int idx = blockIdx.x * blockDim.x + threadIdx.x;
    int node = idx >> 5, lane = idx & 31;
    if (node >= n) return;
    int b = batch[node];
    float4 v = *(const float4*)&h[node * D + lane * 4];
    atomicMax(&g_pool[b * D + lane * 4 + 0], __float_as_uint(v.x));
    atomicMax(&g_pool[b * D + lane * 4 + 1], __float_as_uint(v.y));
    atomicMax(&g_pool[b * D + lane * 4 + 2], __float_as_uint(v.z));
    atomicMax(&g_pool[b * D + lane * 4 + 3], __float_as_uint(v.w));
}

__global__ void k_root(const int* __restrict__ batch, int n) {
    int i = blockIdx.x * blockDim.x + threadIdx.x;
    if (i < n && (i == 0 || batch[i] != batch[i - 1])) g_root[batch[i]] = i;
}

// ---------------- fused MLP head, one block per graph --------------------------
__global__ void __launch_bounds__(128)
k_head(const float* __restrict__ x,
       const float* __restrict__ Wf1, const float* __restrict__ bf1,
       const float* __restrict__ Wf2, const float* __restrict__ bf2,
       const float* __restrict__ Wsm, const float* __restrict__ bsm,
       const float* __restrict__ Wnews, const float* __restrict__ bnews,
       const float* __restrict__ Wcat, const float* __restrict__ bcat,
       float* __restrict__ out) {
    int b = blockIdx.x, t = threadIdx.x;
    __shared__ float p[D], f1[256], f2[D], xr[D], tmp[4];
    p[t] = __uint_as_float(g_pool[b * D + t]);
    int r = g_root[b];
    xr[t] = x[r * D + t];
    __syncthreads();
    for (int o = t; o < 256; o += 128) {
        float a = bf1[o];
        for (int k = 0; k < D; k++) a += p[k] * Wf1[k * 256 + o];
        f1[o] = fmaxf(a, 0.f);
    }
    __syncthreads();
    {
        float a = bf2[t];
        for (int k = 0; k < 256; k++) a += f1[k] * Wf2[k * 128 + t];
        f2[t] = fmaxf(a, 0.f);
    }
    __syncthreads();
    if (t < 2) {
        float a = bsm[t];
        for (int k = 0; k < D; k++) a += f2[k] * Wsm[k * 2 + t];
        tmp[t] = fmaxf(a, 0.f);
    } else if (t < 4) {
        int o = t - 2;
        float a = bnews[o];
        for (int k = 0; k < D; k++) a += xr[k] * Wnews[k * 2 + o];
        tmp[t] = fmaxf(a, 0.f);
    }
    __syncthreads();
    if (t == 0) {
        float z = bcat[0];
        for (int j = 0; j < 4; j++) z += tmp[j] * Wcat[j];
        out[b] = 1.0f / (1.0f + expf(-z));
    }
}

// ---------------- launch -------------------------------------------------------
extern "C" void kernel_launch(void* const* d_in, const int* in_sizes, int n_in,
                              void* d_out, int out_size) {
    const float* x     = (const float*)d_in[0];
    const int*   edge  = (const int*)d_in[1];
    const int*   batch = (const int*)d_in[2];
    const float* Wl1 = (const float*)d_in[3];
    const float* Wr1 = (const float*)d_in[4];
    const float* bl1 = (const float*)d_in[5];
    const float* Wl2 = (const float*)d_in[6];
    const float* Wr2 = (const float*)d_in[7];
    const float* bl2 = (const float*)d_in[8];
    const float* Wl3 = (const float*)d_in[9];
    const float* Wr3 = (const float*)d_in[10];
    const float* bl3 = (const float*)d_in[11];
    const float* Wf1 = (const float*)d_in[12];
    const float* bf1 = (const float*)d_in[13];
    const float* Wf2 = (const float*)d_in[14];
    const float* bf2 = (const float*)d_in[15];
    const float* Wsm = (const float*)d_in[16];
    const float* bsm = (const float*)d_in[17];
    const float* Wnw = (const float*)d_in[18];
    const float* bnw = (const float*)d_in[19];
    const float* Wct = (const float*)d_in[20];
    const float* bct = (const float*)d_in[21];

    int N = in_sizes[0] / D;
    int E = in_sizes[1] / 2;
    int B = out_size;
    const int* src = edge;
    const int* dst = edge + E;

    void* p;
    cudaGetSymbolAddress(&p, g_deg);  cudaMemsetAsync(p, 0, (size_t)N * sizeof(int));
    cudaGetSymbolAddress(&p, g_cur);  cudaMemsetAsync(p, 0, (size_t)N * sizeof(int));
    cudaGetSymbolAddress(&p, g_pool); cudaMemsetAsync(p, 0, (size_t)B * D * sizeof(unsigned));

    float *yp, *rp, *hA, *hB;
    cudaGetSymbolAddress((void**)&yp, g_y);
    cudaGetSymbolAddress((void**)&rp, g_r);
    cudaGetSymbolAddress((void**)&hA, g_hA);
    cudaGetSymbolAddress((void**)&hB, g_hB);

    k_count<<<(E + 255) / 256, 256>>>(dst, E);
    k_scan<<<1, 1024>>>(N);
    k_fill<<<(E + 255) / 256, 256>>>(src, dst, E);

    size_t smem = (size_t)(D * 256 + BM * D) * sizeof(float);  // 160 KB
    cudaFuncSetAttribute(k_gemm, cudaFuncAttributeMaxDynamicSharedMemorySize, (int)smem);
    int gb = (N + BM - 1) / BM;
    int ga = ((N * 32) + 255) / 256;

    // layer 1: x -> hA
    k_gemm<<<gb, 256, smem>>>(x, Wl1, Wr1, yp, rp, N);
    k_agg<<<ga, 256>>>(yp, rp, bl1, hA, N);
    // layer 2: hA -> hB
    k_gemm<<<gb, 256, smem>>>(hA, Wl2, Wr2, yp, rp, N);
    k_agg<<<ga, 256>>>(yp, rp, bl2, hB, N);
    // layer 3: hB -> hA
    k_gemm<<<gb, 256, smem>>>(hB, Wl3, Wr3, yp, rp, N);
    k_agg<<<ga, 256>>>(yp, rp, bl3, hA, N);

    k_pool<<<ga, 256>>>(hA, batch, N);
    k_root<<<(N + 255) / 256, 256>>>(batch, N);
    k_head<<<B, 128>>>(x, Wf1, bf1, Wf2, bf2, Wsm, bsm, Wnw, bnw, Wct, bct, (float*)d_out);
}

// round 9
// speedup vs baseline: 1.0020x; 1.0008x over previous
#include <cuda_runtime.h>
#include <math.h>

#define D 128
#define MAXN 50048
#define MAXE 800000
#define MAXB 1024
#define BM 64

// ---------------- device scratch (static globals: allocation-free) -------------
__device__ int g_deg[MAXN];
__device__ int g_off[MAXN + 1];
__device__ int g_cur[MAXN];
__device__ int g_csr[MAXE];
__device__ float g_y[MAXN * D];   // x @ Wl  (pre-aggregation messages)
__device__ float g_r[MAXN * D];   // x @ Wr  (self term)
__device__ float g_hA[MAXN * D];
__device__ float g_hB[MAXN * D];
__device__ unsigned g_pool[MAXB * D];
__device__ int g_root[MAXB];

// ---------------- CSR build ---------------------------------------------------
__global__ void k_count(const int* __restrict__ dst, int E) {
    int e = blockIdx.x * blockDim.x + threadIdx.x;
    if (e < E) atomicAdd(&g_deg[dst[e]], 1);
}

// single-block inclusive scan over degrees -> exclusive offsets
__global__ void k_scan(int n) {
    __shared__ int s[1024];
    __shared__ int carry;
    int tid = threadIdx.x;
    if (tid == 0) { carry = 0; g_off[0] = 0; }
    __syncthreads();
    for (int base = 0; base < n; base += 1024) {
        int v = (base + tid < n) ? g_deg[base + tid] : 0;
        s[tid] = v;
        __syncthreads();
        for (int d2 = 1; d2 < 1024; d2 <<= 1) {
            int t = (tid >= d2) ? s[tid - d2] : 0;
            __syncthreads();
            s[tid] += t;
            __syncthreads();
        }
        int total = s[1023];
        if (base + tid < n) g_off[base + tid + 1] = carry + s[tid];
        __syncthreads();
        if (tid == 0) carry += total;
        __syncthreads();
    }
}

__global__ void k_fill(const int* __restrict__ src, const int* __restrict__ dst, int E) {
    int e = blockIdx.x * blockDim.x + threadIdx.x;
    if (e < E) {
        int d = dst[e];
        int p = atomicAdd(&g_cur[d], 1);
        g_csr[g_off[d] + p] = src[e];
    }
}

// ---------------- fused dual GEMM: y = feat@Wl, r = feat@Wr -------------------
// BM=64 rows/block, 256 output cols (128 for Wl, 128 for Wr), K=128 in one shot.
// 256 threads, thread tile 4 rows x 16 cols. Weights + feat tile in dyn smem.
__global__ void __launch_bounds__(256)
k_gemm(const float* __restrict__ feat, const float* __restrict__ Wl,
       const float* __restrict__ Wr, float* __restrict__ y,
       float* __restrict__ r, int n) {
    extern __shared__ float smem[];
    float* Ws = smem;              // [128][256] = 128 KB
    float* As = smem + D * 256;    // [64][128]  =  32 KB
    int tid = threadIdx.x;

    // load weights into smem, Ws[k][c]: c<128 -> Wl, c>=128 -> Wr
    const float4* wl4 = (const float4*)Wl;
    const float4* wr4 = (const float4*)Wr;
    for (int i = tid; i < D * D / 4; i += 256) {
        int k = (i * 4) / D, c = (i * 4) % D;
        *(float4*)&Ws[k * 256 + c]       = wl4[i];
        *(float4*)&Ws[k * 256 + c + 128] = wr4[i];
    }
    // load 64-row feature tile
    int rb = blockIdx.x * BM;
    const float4* f4 = (const float4*)feat;
    for (int i = tid; i < BM * D / 4; i += 256) {
        int rr = (i * 4) / D, cc = (i * 4) % D;
        int row = rb + rr;
        float4 v = make_float4(0.f, 0.f, 0.f, 0.f);
        if (row < n) v = f4[row * (D / 4) + cc / 4];
        *(float4*)&As[rr * D + cc] = v;
    }
    __syncthreads();

    int ty = tid >> 4, tx = tid & 15;
    float acc[4][16];
#pragma unroll
    for (int i = 0; i < 4; i++)
#pragma unroll
        for (int j = 0; j < 16; j++) acc[i][j] = 0.f;

#pragma unroll 4
    for (int k = 0; k < D; k++) {
        float a[4];
#pragma unroll
        for (int i = 0; i < 4; i++) a[i] = As[(ty * 4 + i) * D + k];
        float bb[16];
#pragma unroll
        for (int j = 0; j < 16; j += 4)
            *(float4*)&bb[j] = *(const float4*)&Ws[k * 256 + tx * 16 + j];
#pragma unroll
        for (int i = 0; i < 4; i++)
#pragma unroll
            for (int j = 0; j < 16; j++) acc[i][j] += a[i] * bb[j];
    }

#pragma unroll
    for (int i = 0; i < 4; i++) {
        int row = rb + ty * 4 + i;
        if (row >= n) continue;
#pragma unroll
        for (int j = 0; j < 16; j += 4) {
            int c = tx * 16 + j;
            float4 v = make_float4(acc[i][j], acc[i][j + 1], acc[i][j + 2], acc[i][j + 3]);
            if (c < 128) *(float4*)&y[row * D + c] = v;
            else         *(float4*)&r[row * D + (c - 128)] = v;
        }
    }
}

// ---------------- per-node mean aggregation + bias + self + relu --------------
// one warp per node; lane l owns 4 contiguous floats of the 128-dim row
__global__ void k_agg(const float* __restrict__ yl, const float* __restrict__ hr,
                      const float* __restrict__ bl, float* __restrict__ out, int n) {
    int warp = (blockIdx.x * blockDim.x + threadIdx.x) >> 5;
    int lane = threadIdx.x & 31;
    if (warp >= n) return;
    int beg = g_off[warp], end = g_off[warp + 1];
    float4 acc = make_float4(0.f, 0.f, 0.f, 0.f);
    for (int e = beg; e < end; e++) {
        int j = __ldg(&g_csr[e]);
        float4 v = *(const float4*)&yl[j * D + lane * 4];
        acc.x += v.x; acc.y += v.y; acc.z += v.z; acc.w += v.w;
    }
    float inv = 1.0f / fmaxf((float)(end - beg), 1.0f);
    float4 b = *(const float4*)&bl[lane * 4];
    float4 rr = *(const float4*)&hr[warp * D + lane * 4];
    float4 o;
    o.x = fmaxf(acc.x * inv + b.x + rr.x, 0.f);
    o.y = fmaxf(acc.y * inv + b.y + rr.y, 0.f);
    o.z = fmaxf(acc.z * inv + b.z + rr.z, 0.f);
    o.w = fmaxf(acc.w * inv + b.w + rr.w, 0.f);
    *(float4*)&out[warp * D + lane * 4] = o;
}

// ---------------- global max pool (uint-bit atomicMax, values >= 0) -----------
__global__ void k_pool(const float* __restrict__ h, const int* __restrict__ batch, int n) {
    int idx = blockIdx.x * blockDim.x + threadIdx.x;
    int node = idx >> 5, lane = idx & 31;
    if (node >= n) return;
    int b = batch[node];
    float4 v = *(const float4*)&h[node * D + lane * 4];
    atomicMax(&g_pool[b * D + lane * 4 + 0], __float_as_uint(v.x));
    atomicMax(&g_pool[b * D + lane * 4 + 1], __float_as_uint(v.y));
    atomicMax(&g_pool[b * D + lane * 4 + 2], __float_as_uint(v.z));
    atomicMax(&g_pool[b * D + lane * 4 + 3], __float_as_uint(v.w));
}

__global__ void k_root(const int* __restrict__ batch, int n) {
    int i = blockIdx.x * blockDim.x + threadIdx.x;
    if (i < n && (i == 0 || batch[i] != batch[i - 1])) g_root[batch[i]] = i;
}

// ---------------- fused MLP head, one block per graph --------------------------
__global__ void __launch_bounds__(128)
k_head(const float* __restrict__ x,
       const float* __restrict__ Wf1, const float* __restrict__ bf1,
       const float* __restrict__ Wf2, const float* __restrict__ bf2,
       const float* __restrict__ Wsm, const float* __restrict__ bsm,
       const float* __restrict__ Wnews, const float* __restrict__ bnews,
       const float* __restrict__ Wcat, const float* __restrict__ bcat,
       float* __restrict__ out) {
    int b = blockIdx.x, t = threadIdx.x;
    __shared__ float p[D], f1[256], f2[D], xr[D], tmp[4];
    p[t] = __uint_as_float(g_pool[b * D + t]);
    int r = g_root[b];
    xr[t] = x[r * D + t];
    __syncthreads();
    for (int o = t; o < 256; o += 128) {
        float a = bf1[o];
        for (int k = 0; k < D; k++) a += p[k] * Wf1[k * 256 + o];
        f1[o] = fmaxf(a, 0.f);
    }
    __syncthreads();
    {
        float a = bf2[t];
        for (int k = 0; k < 256; k++) a += f1[k] * Wf2[k * 128 + t];
        f2[t] = fmaxf(a, 0.f);
    }
    __syncthreads();
    if (t < 2) {
        float a = bsm[t];
        for (int k = 0; k < D; k++) a += f2[k] * Wsm[k * 2 + t];
        tmp[t] = fmaxf(a, 0.f);
    } else if (t < 4) {
        int o = t - 2;
        float a = bnews[o];
        for (int k = 0; k < D; k++) a += xr[k] * Wnews[k * 2 + o];
        tmp[t] = fmaxf(a, 0.f);
    }
    __syncthreads();
    if (t == 0) {
        float z = bcat[0];
        for (int j = 0; j < 4; j++) z += tmp[j] * Wcat[j];
        out[b] = 1.0f / (1.0f + expf(-z));
    }
}

// ---------------- launch -------------------------------------------------------
extern "C" void kernel_launch(void* const* d_in, const int* in_sizes, int n_in,
                              void* d_out, int out_size) {
    const float* x     = (const float*)d_in[0];
    const int*   edge  = (const int*)d_in[1];
    const int*   batch = (const int*)d_in[2];
    const float* Wl1 = (const float*)d_in[3];
    const float* Wr1 = (const float*)d_in[4];
    const float* bl1 = (const float*)d_in[5];
    const float* Wl2 = (const float*)d_in[6];
    const float* Wr2 = (const float*)d_in[7];
    const float* bl2 = (const float*)d_in[8];
    const float* Wl3 = (const float*)d_in[9];
    const float* Wr3 = (const float*)d_in[10];
    const float* bl3 = (const float*)d_in[11];
    const float* Wf1 = (const float*)d_in[12];
    const float* bf1 = (const float*)d_in[13];
    const float* Wf2 = (const float*)d_in[14];
    const float* bf2 = (const float*)d_in[15];
    const float* Wsm = (const float*)d_in[16];
    const float* bsm = (const float*)d_in[17];
    const float* Wnw = (const float*)d_in[18];
    const float* bnw = (const float*)d_in[19];
    const float* Wct = (const float*)d_in[20];
    const float* bct = (const float*)d_in[21];

    int N = in_sizes[0] / D;
    int E = in_sizes[1] / 2;
    int B = out_size;
    const int* src = edge;
    const int* dst = edge + E;

    void* p;
    cudaGetSymbolAddress(&p, g_deg);  cudaMemsetAsync(p, 0, (size_t)N * sizeof(int));
    cudaGetSymbolAddress(&p, g_cur);  cudaMemsetAsync(p, 0, (size_t)N * sizeof(int));
    cudaGetSymbolAddress(&p, g_pool); cudaMemsetAsync(p, 0, (size_t)B * D * sizeof(unsigned));

    float *yp, *rp, *hA, *hB;
    cudaGetSymbolAddress((void**)&yp, g_y);
    cudaGetSymbolAddress((void**)&rp, g_r);
    cudaGetSymbolAddress((void**)&hA, g_hA);
    cudaGetSymbolAddress((void**)&hB, g_hB);

    k_count<<<(E + 255) / 256, 256>>>(dst, E);
    k_scan<<<1, 1024>>>(N);
    k_fill<<<(E + 255) / 256, 256>>>(src, dst, E);

    size_t smem = (size_t)(D * 256 + BM * D) * sizeof(float);  // 160 KB
    cudaFuncSetAttribute(k_gemm, cudaFuncAttributeMaxDynamicSharedMemorySize, (int)smem);
    int gb = (N + BM - 1) / BM;
    int ga = ((N * 32) + 255) / 256;

    // layer 1: x -> hA
    k_gemm<<<gb, 256, smem>>>(x, Wl1, Wr1, yp, rp, N);
    k_agg<<<ga, 256>>>(yp, rp, bl1, hA, N);
    // layer 2: hA -> hB
    k_gemm<<<gb, 256, smem>>>(hA, Wl2, Wr2, yp, rp, N);
    k_agg<<<ga, 256>>>(yp, rp, bl2, hB, N);
    // layer 3: hB -> hA
    k_gemm<<<gb, 256, smem>>>(hB, Wl3, Wr3, yp, rp, N);
    k_agg<<<ga, 256>>>(yp, rp, bl3, hA, N);

    k_pool<<<ga, 256>>>(hA, batch, N);
    k_root<<<(N + 255) / 256, 256>>>(batch, N);
    k_head<<<B, 128>>>(x, Wf1, bf1, Wf2, bf2, Wsm, bsm, Wnw, bnw, Wct, bct, (float*)d_out);
}

// round 10
// speedup vs baseline: 1.6765x; 1.6731x over previous
#include <cuda_runtime.h>
#include <math.h>

#define D 128
#define MAXN 50048
#define MAXE 800000
#define MAXB 1024
#define BM 64

// ---------------- device scratch (static globals: allocation-free) -------------
__device__ int g_deg[MAXN];
__device__ int g_off[MAXN + 1];
__device__ int g_cur[MAXN];
__device__ int g_csr[MAXE];
__device__ float g_y[MAXN * D];   // x @ Wl  (pre-aggregation messages)
__device__ float g_r[MAXN * D];   // x @ Wr  (self term)
__device__ float g_hA[MAXN * D];
__device__ float g_hB[MAXN * D];
__device__ unsigned g_pool[MAXB * D];
__device__ int g_root[MAXB];

// ---------------- CSR build ---------------------------------------------------
__global__ void k_count(const int* __restrict__ dst, int E) {
    int e = blockIdx.x * blockDim.x + threadIdx.x;
    if (e < E) atomicAdd(&g_deg[dst[e]], 1);
}

// single-block inclusive scan over degrees -> exclusive offsets
__global__ void k_scan(int n) {
    __shared__ int s[1024];
    __shared__ int carry;
    int tid = threadIdx.x;
    if (tid == 0) { carry = 0; g_off[0] = 0; }
    __syncthreads();
    for (int base = 0; base < n; base += 1024) {
        int v = (base + tid < n) ? g_deg[base + tid] : 0;
        s[tid] = v;
        __syncthreads();
        for (int d2 = 1; d2 < 1024; d2 <<= 1) {
            int t = (tid >= d2) ? s[tid - d2] : 0;
            __syncthreads();
            s[tid] += t;
            __syncthreads();
        }
        int total = s[1023];
        if (base + tid < n) g_off[base + tid + 1] = carry + s[tid];
        __syncthreads();
        if (tid == 0) carry += total;
        __syncthreads();
    }
}

__global__ void k_fill(const int* __restrict__ src, const int* __restrict__ dst, int E) {
    int e = blockIdx.x * blockDim.x + threadIdx.x;
    if (e < E) {
        int d = dst[e];
        int p = atomicAdd(&g_cur[d], 1);
        g_csr[g_off[d] + p] = src[e];
    }
}

// ---------------- GEMM: out = feat @ W  (one of Wl/Wr per blockIdx.y) ---------
// BM=64 rows/block, BN=128 cols, K=128 in one shot. 256 threads, 4x8 per thread.
// A-tile stored K-MAJOR in smem (conflict-free broadcast a-loads).
// B cols split as {tx*4, tx*4+64}: 16 contiguous float4 chunks -> conflict-free.
// smem = 64KB (W) + 32KB (A) = 96KB -> 2 CTAs/SM.
__global__ void __launch_bounds__(256, 2)
k_gemm(const float* __restrict__ feat, const float* __restrict__ Wl,
       const float* __restrict__ Wr, float* __restrict__ y,
       float* __restrict__ r, int n) {
    extern __shared__ float smem[];
    float* Ws = smem;            // [128][128] k-major (natural layout)
    float* As = smem + D * D;    // [128][64]  k-major
    const float* W = blockIdx.y ? Wr : Wl;
    float* out    = blockIdx.y ? r  : y;
    int tid = threadIdx.x;

    // stage weights (natural [k][c] layout)
    {
        const float4* w4 = (const float4*)W;
        float4* ws4 = (float4*)Ws;
#pragma unroll 4
        for (int i = tid; i < D * D / 4; i += 256) ws4[i] = w4[i];
    }
    // stage 64-row feature tile, transposed to k-major: As[k*64 + row]
    int rb = blockIdx.x * BM;
    {
        const float4* f4 = (const float4*)feat;
#pragma unroll 4
        for (int i = tid; i < BM * (D / 4); i += 256) {
            int rr = i / (D / 4), c4 = i % (D / 4);
            float4 v = make_float4(0.f, 0.f, 0.f, 0.f);
            int row = rb + rr;
            if (row < n) v = f4[row * (D / 4) + c4];
            int k0 = c4 * 4;
            As[(k0 + 0) * BM + rr] = v.x;
            As[(k0 + 1) * BM + rr] = v.y;
            As[(k0 + 2) * BM + rr] = v.z;
            As[(k0 + 3) * BM + rr] = v.w;
        }
    }
    __syncthreads();

    int ty = tid >> 4, tx = tid & 15;  // ty: row group, tx: col group
    float acc[4][8];
#pragma unroll
    for (int i = 0; i < 4; i++)
#pragma unroll
        for (int j = 0; j < 8; j++) acc[i][j] = 0.f;

#pragma unroll 8
    for (int k = 0; k < D; k++) {
        float4 a  = *(const float4*)&As[k * BM + ty * 4];
        float4 b0 = *(const float4*)&Ws[k * D + tx * 4];
        float4 b1 = *(const float4*)&Ws[k * D + tx * 4 + 64];
        float av[4] = {a.x, a.y, a.z, a.w};
        float bv[8] = {b0.x, b0.y, b0.z, b0.w, b1.x, b1.y, b1.z, b1.w};
#pragma unroll
        for (int i = 0; i < 4; i++)
#pragma unroll
            for (int j = 0; j < 8; j++) acc[i][j] += av[i] * bv[j];
    }

#pragma unroll
    for (int i = 0; i < 4; i++) {
        int row = rb + ty * 4 + i;
        if (row >= n) continue;
        float4 v0 = make_float4(acc[i][0], acc[i][1], acc[i][2], acc[i][3]);
        float4 v1 = make_float4(acc[i][4], acc[i][5], acc[i][6], acc[i][7]);
        *(float4*)&out[row * D + tx * 4]      = v0;
        *(float4*)&out[row * D + tx * 4 + 64] = v1;
    }
}

// ---------------- per-node mean aggregation + bias + self + relu --------------
// one warp per node; lane l owns 4 contiguous floats of the 128-dim row
__global__ void k_agg(const float* __restrict__ yl, const float* __restrict__ hr,
                      const float* __restrict__ bl, float* __restrict__ out, int n) {
    int warp = (blockIdx.x * blockDim.x + threadIdx.x) >> 5;
    int lane = threadIdx.x & 31;
    if (warp >= n) return;
    int beg = g_off[warp], end = g_off[warp + 1];
    float4 acc = make_float4(0.f, 0.f, 0.f, 0.f);
    for (int e = beg; e < end; e++) {
        int j = __ldg(&g_csr[e]);
        float4 v = *(const float4*)&yl[j * D + lane * 4];
        acc.x += v.x; acc.y += v.y; acc.z += v.z; acc.w += v.w;
    }
    float inv = 1.0f / fmaxf((float)(end - beg), 1.0f);
    float4 b = *(const float4*)&bl[lane * 4];
    float4 rr = *(const float4*)&hr[warp * D + lane * 4];
    float4 o;
    o.x = fmaxf(acc.x * inv + b.x + rr.x, 0.f);
    o.y = fmaxf(acc.y * inv + b.y + rr.y, 0.f);
    o.z = fmaxf(acc.z * inv + b.z + rr.z, 0.f);
    o.w = fmaxf(acc.w * inv + b.w + rr.w, 0.f);
    *(float4*)&out[warp * D + lane * 4] = o;
}

// ---------------- global max pool (uint-bit atomicMax, values >= 0) -----------
__global__ void k_pool(const float* __restrict__ h, const int* __restrict__ batch, int n) {
    int idx = blockIdx.x * blockDim.x + threadIdx.x;
    int node = idx >> 5, lane = idx & 31;
    if (node >= n) return;
    int b = batch[node];
    float4 v = *(const float4*)&h[node * D + lane * 4];
    atomicMax(&g_pool[b * D + lane * 4 + 0], __float_as_uint(v.x));
    atomicMax(&g_pool[b * D + lane * 4 + 1], __float_as_uint(v.y));
    atomicMax(&g_pool[b * D + lane * 4 + 2], __float_as_uint(v.z));
    atomicMax(&g_pool[b * D + lane * 4 + 3], __float_as_uint(v.w));
}

__global__ void k_root(const int* __restrict__ batch, int n) {
    int i = blockIdx.x * blockDim.x + threadIdx.x;
    if (i < n && (i == 0 || batch[i] != batch[i - 1])) g_root[batch[i]] = i;
}

// ---------------- fused MLP head, one block per graph --------------------------
__global__ void __launch_bounds__(128)
k_head(const float* __restrict__ x,
       const float* __restrict__ Wf1, const float* __restrict__ bf1,
       const float* __restrict__ Wf2, const float* __restrict__ bf2,
       const float* __restrict__ Wsm, const float* __restrict__ bsm,
       const float* __restrict__ Wnews, const float* __restrict__ bnews,
       const float* __restrict__ Wcat, const float* __restrict__ bcat,
       float* __restrict__ out) {
    int b = blockIdx.x, t = threadIdx.x;
    __shared__ float p[D], f1[256], f2[D], xr[D], tmp[4];
    p[t] = __uint_as_float(g_pool[b * D + t]);
    int r = g_root[b];
    xr[t] = x[r * D + t];
    __syncthreads();
    for (int o = t; o < 256; o += 128) {
        float a = bf1[o];
        for (int k = 0; k < D; k++) a += p[k] * Wf1[k * 256 + o];
        f1[o] = fmaxf(a, 0.f);
    }
    __syncthreads();
    {
        float a = bf2[t];
        for (int k = 0; k < 256; k++) a += f1[k] * Wf2[k * 128 + t];
        f2[t] = fmaxf(a, 0.f);
    }
    __syncthreads();
    if (t < 2) {
        float a = bsm[t];
        for (int k = 0; k < D; k++) a += f2[k] * Wsm[k * 2 + t];
        tmp[t] = fmaxf(a, 0.f);
    } else if (t < 4) {
        int o = t - 2;
        float a = bnews[o];
        for (int k = 0; k < D; k++) a += xr[k] * Wnews[k * 2 + o];
        tmp[t] = fmaxf(a, 0.f);
    }
    __syncthreads();
    if (t == 0) {
        float z = bcat[0];
        for (int j = 0; j < 4; j++) z += tmp[j] * Wcat[j];
        out[b] = 1.0f / (1.0f + expf(-z));
    }
}

// ---------------- launch -------------------------------------------------------
extern "C" void kernel_launch(void* const* d_in, const int* in_sizes, int n_in,
                              void* d_out, int out_size) {
    const float* x     = (const float*)d_in[0];
    const int*   edge  = (const int*)d_in[1];
    const int*   batch = (const int*)d_in[2];
    const float* Wl1 = (const float*)d_in[3];
    const float* Wr1 = (const float*)d_in[4];
    const float* bl1 = (const float*)d_in[5];
    const float* Wl2 = (const float*)d_in[6];
    const float* Wr2 = (const float*)d_in[7];
    const float* bl2 = (const float*)d_in[8];
    const float* Wl3 = (const float*)d_in[9];
    const float* Wr3 = (const float*)d_in[10];
    const float* bl3 = (const float*)d_in[11];
    const float* Wf1 = (const float*)d_in[12];
    const float* bf1 = (const float*)d_in[13];
    const float* Wf2 = (const float*)d_in[14];
    const float* bf2 = (const float*)d_in[15];
    const float* Wsm = (const float*)d_in[16];
    const float* bsm = (const float*)d_in[17];
    const float* Wnw = (const float*)d_in[18];
    const float* bnw = (const float*)d_in[19];
    const float* Wct = (const float*)d_in[20];
    const float* bct = (const float*)d_in[21];

    int N = in_sizes[0] / D;
    int E = in_sizes[1] / 2;
    int B = out_size;
    const int* src = edge;
    const int* dst = edge + E;

    void* p;
    cudaGetSymbolAddress(&p, g_deg);  cudaMemsetAsync(p, 0, (size_t)N * sizeof(int));
    cudaGetSymbolAddress(&p, g_cur);  cudaMemsetAsync(p, 0, (size_t)N * sizeof(int));
    cudaGetSymbolAddress(&p, g_pool); cudaMemsetAsync(p, 0, (size_t)B * D * sizeof(unsigned));

    float *yp, *rp, *hA, *hB;
    cudaGetSymbolAddress((void**)&yp, g_y);
    cudaGetSymbolAddress((void**)&rp, g_r);
    cudaGetSymbolAddress((void**)&hA, g_hA);
    cudaGetSymbolAddress((void**)&hB, g_hB);

    k_count<<<(E + 255) / 256, 256>>>(dst, E);
    k_scan<<<1, 1024>>>(N);
    k_fill<<<(E + 255) / 256, 256>>>(src, dst, E);

    size_t smem = (size_t)(D * D + D * BM) * sizeof(float);  // 96 KB
    cudaFuncSetAttribute(k_gemm, cudaFuncAttributeMaxDynamicSharedMemorySize, (int)smem);
    dim3 gb((N + BM - 1) / BM, 2);
    int ga = ((N * 32) + 255) / 256;

    // layer 1: x -> hA
    k_gemm<<<gb, 256, smem>>>(x, Wl1, Wr1, yp, rp, N);
    k_agg<<<ga, 256>>>(yp, rp, bl1, hA, N);
    // layer 2: hA -> hB
    k_gemm<<<gb, 256, smem>>>(hA, Wl2, Wr2, yp, rp, N);
    k_agg<<<ga, 256>>>(yp, rp, bl2, hB, N);
    // layer 3: hB -> hA
    k_gemm<<<gb, 256, smem>>>(hB, Wl3, Wr3, yp, rp, N);
    k_agg<<<ga, 256>>>(yp, rp, bl3, hA, N);

    k_pool<<<ga, 256>>>(hA, batch, N);
    k_root<<<(N + 255) / 256, 256>>>(batch, N);
    k_head<<<B, 128>>>(x, Wf1, bf1, Wf2, bf2, Wsm, bsm, Wnw, bnw, Wct, bct, (float*)d_out);
}